// round 7
// baseline (speedup 1.0000x reference)
#include <cuda_runtime.h>
#include <cuda_fp16.h>
#include <stdint.h>
#include <math.h>

// Problem constants
#define NTOK   32768
#define CDIM   512
#define KCODES 1024
#define QSTG   6
#define NB     64
#define TLEN   512

#define OUT_IDX_OFF  (NB * CDIM * TLEN)
#define OUT_SCAL_OFF (OUT_IDX_OFF + NTOK * QSTG)

// ---- static device scratch ----
__device__ __align__(256) float  g_resid[(size_t)NTOK * CDIM];
__device__ __align__(256) __half g_rHi[(size_t)NTOK * CDIM];
__device__ __align__(256) __half g_rLo[(size_t)NTOK * CDIM];
__device__ __align__(256) __half g_cbHi[(size_t)QSTG * KCODES * CDIM];
__device__ __align__(256) __half g_cbLo[(size_t)QSTG * KCODES * CDIM];
__device__ float        g_cnorm[QSTG * KCODES];
__device__ int          g_idx[QSTG * NTOK];
__device__ unsigned int g_hist[QSTG * KCODES];
__device__ float        g_lossPart[QSTG][NTOK / 128];

// ---- dynamic SMEM layout ----
#define SM_CN     0          // 1024 floats  (4 KB)
#define SM_SD     4096       // 2*128 floats (1 KB)
#define SM_SI     5120       // 2*128 ints   (1 KB)
#define SM_RED    6144       // 256 floats   (1 KB)
#define SM_BESTI  7168       // 128 ints
#define SM_TILES  8192       // 3 stages x (A 16 KB + B 16 KB)
#define STG_BYTES 32768
#define SMEM_TOTAL (8192 + 3 * STG_BYTES)   // 106496

static __device__ __forceinline__ uint32_t smem_u32(const void* p) {
    uint32_t a;
    asm("{ .reg .u64 t; cvta.to.shared.u64 t, %1; cvt.u32.u64 %0, t; }" : "=r"(a) : "l"(p));
    return a;
}

#define CP16(dst, src) \
    asm volatile("cp.async.cg.shared.global [%0], [%1], 16;" :: "r"(dst), "l"(src))
#define CP_COMMIT() asm volatile("cp.async.commit_group;" ::: "memory")

#define LDSM_X4(r0, r1, r2, r3, addr)                                          \
    asm volatile("ldmatrix.sync.aligned.m8n8.x4.shared.b16 {%0,%1,%2,%3}, [%4];" \
        : "=r"(r0), "=r"(r1), "=r"(r2), "=r"(r3) : "r"(addr))

#define MMA16816(d, a, b)                                                      \
    asm volatile("mma.sync.aligned.m16n8k16.row.col.f32.f16.f16.f32 "          \
        "{%0,%1,%2,%3}, {%4,%5,%6,%7}, {%8,%9}, {%0,%1,%2,%3};"                \
        : "+f"((d)[0]), "+f"((d)[1]), "+f"((d)[2]), "+f"((d)[3])               \
        : "r"((a)[0]), "r"((a)[1]), "r"((a)[2]), "r"((a)[3]),                  \
          "r"((b)[0]), "r"((b)[1]))

// one 128x64-half tile, XOR-swizzled 16B chunks, 4 cp.async per thread
static __device__ __forceinline__ void load_tile(
    uint32_t sbase, uint32_t dstOff, const __half* __restrict__ src,
    int rowOff, int kOff, int tid)
{
#pragma unroll
    for (int t = 0; t < 4; t++) {
        int ci = tid + 256 * t;
        int row = ci >> 3, ch = ci & 7;
        const void* s = src + (size_t)(rowOff + row) * CDIM + kOff + ch * 8;
        uint32_t d = sbase + dstOff + row * 128 + ((ch ^ (row & 7)) << 4);
        CP16(d, s);
    }
}

// ---------------------------------------------------------------------------
__global__ void init_kernel() {
    int i = blockIdx.x * blockDim.x + threadIdx.x;
    if (i < QSTG * KCODES) g_hist[i] = 0u;
}

// per-code: fp16 hi/lo split of codebook + |c|^2
__global__ void prep_cb(const float* __restrict__ cb) {
    __shared__ float red[4];
    int code = blockIdx.x;                    // q*1024 + k
    int tid = threadIdx.x;
    size_t base = (size_t)code * CDIM;
    float4 v = ((const float4*)(cb + base))[tid];
    __half h0 = __float2half(v.x), h1 = __float2half(v.y);
    __half h2 = __float2half(v.z), h3 = __float2half(v.w);
    *(__half2*)&g_cbHi[base + tid * 4]     = __halves2half2(h0, h1);
    *(__half2*)&g_cbHi[base + tid * 4 + 2] = __halves2half2(h2, h3);
    *(__half2*)&g_cbLo[base + tid * 4] = __halves2half2(
        __float2half(v.x - __half2float(h0)), __float2half(v.y - __half2float(h1)));
    *(__half2*)&g_cbLo[base + tid * 4 + 2] = __halves2half2(
        __float2half(v.z - __half2float(h2)), __float2half(v.w - __half2float(h3)));
    float s = v.x * v.x + v.y * v.y + v.z * v.z + v.w * v.w;
#pragma unroll
    for (int off = 16; off > 0; off >>= 1) s += __shfl_down_sync(0xffffffffu, s, off);
    if ((tid & 31) == 0) red[tid >> 5] = s;
    __syncthreads();
    if (tid == 0) g_cnorm[code] = red[0] + red[1] + red[2] + red[3];
}

// transpose x -> residual (NT, C) + fp16 hi/lo
__global__ void prep_resid(const float* __restrict__ x) {
    __shared__ float tile[32][33];
    int n = blockIdx.z;
    int tBase = blockIdx.x * 32;
    int cBase = blockIdx.y * 32;
    int tx = threadIdx.x, ty = threadIdx.y;
#pragma unroll
    for (int j = 0; j < 4; j++)
        tile[ty + j * 8][tx] =
            x[(size_t)n * CDIM * TLEN + (size_t)(cBase + ty + j * 8) * TLEN + tBase + tx];
    __syncthreads();
#pragma unroll
    for (int j = 0; j < 4; j++) {
        float v = tile[tx][ty + j * 8];
        size_t o = (size_t)(n * TLEN + tBase + ty + j * 8) * CDIM + cBase + tx;
        g_resid[o] = v;
        __half h = __float2half(v);
        g_rHi[o] = h;
        g_rLo[o] = __float2half(v - __half2float(h));
    }
}

// ---------------------------------------------------------------------------
// HMMA stage kernel: 3-segment fp16-split GEMM + argmin + residual update
// Flat 192-iteration mainloop (8 n-chunks x 24 k-blocks), 3-stage cp.async
// pipeline.  Order per iteration: wait_group -> barrier -> compute -> prefetch.
// The barrier AFTER the wait makes all threads' group-u data visible before
// any thread reads the tile; it also proves compute u-1 is done everywhere
// before stage (u-1)%3 is overwritten by prefetch(u+2).
// ---------------------------------------------------------------------------
__global__ __launch_bounds__(256, 2)
void vq_stage_mma(const float* __restrict__ cbF32, int q) {
    extern __shared__ char smem[];
    uint32_t sbase = smem_u32(smem);
    const int tid = threadIdx.x;
    const int lane = tid & 31;
    const int wid = tid >> 5;
    const int wm = wid & 3;        // m-group: rows wm*32..+32
    const int wn = wid >> 2;       // n-group: cols wn*64..+64
    const int rowBase = blockIdx.x * 128;

    float* sCn = (float*)(smem + SM_CN);
#pragma unroll
    for (int i = 0; i < 4; i++) sCn[tid + 256 * i] = g_cnorm[q * KCODES + tid + 256 * i];

    const __half* cHi = g_cbHi + (size_t)q * KCODES * CDIM;
    const __half* cLo = g_cbLo + (size_t)q * KCODES * CDIM;
    const __half* srcA[3] = {g_rHi, g_rHi, g_rLo};
    const __half* srcB[3] = {cHi, cLo, cHi};

    float bestD[4];
    int   bestI[4];
#pragma unroll
    for (int i = 0; i < 4; i++) { bestD[i] = 3.4e38f; bestI[i] = 0; }

    // per-lane ldmatrix address components
    const int aRow0 = wm * 32 + (lane & 15);       // + mt*16
    const int aChB  = lane >> 4;                   // + ks*2
    const int bN0   = wn * 64 + ((lane >> 4) << 3) + (lane & 7);  // + ntp*16
    const int bChB  = (lane >> 3) & 1;             // + ks*2

    float acc[2][8][4];
#pragma unroll
    for (int mt = 0; mt < 2; mt++)
#pragma unroll
        for (int nt = 0; nt < 8; nt++)
#pragma unroll
            for (int c = 0; c < 4; c++) acc[mt][nt][c] = 0.f;

    // prefetch iteration v into pipeline stage v%3 (own commit group each)
    // iteration v: nc = v/24, s = v%24, seg = s/8, kb = s%8
#define PREFETCH(v) do {                                                       \
        int _nc = (v) / 24, _s = (v) % 24;                                     \
        int _seg = _s >> 3, _kb = _s & 7;                                      \
        uint32_t _off = SM_TILES + ((v) % 3) * STG_BYTES;                      \
        load_tile(sbase, _off,         srcA[_seg], rowBase,   _kb * 64, tid);  \
        load_tile(sbase, _off + 16384, srcB[_seg], _nc * 128, _kb * 64, tid);  \
        CP_COMMIT();                                                           \
    } while (0)

    PREFETCH(0);
    PREFETCH(1);

    for (int u = 0; u < 192; u++) {
        // wait for own group u (pending: {u, u+1} in steady state; {191} at tail)
        if (u < 191) {
            asm volatile("cp.async.wait_group 1;" ::: "memory");
        } else {
            asm volatile("cp.async.wait_group 0;" ::: "memory");
        }
        // collective visibility of group-u data + release of stage (u-1)%3
        __syncthreads();

        uint32_t As = sbase + SM_TILES + (u % 3) * STG_BYTES;
        uint32_t Bs = As + 16384;
#pragma unroll
        for (int ks = 0; ks < 4; ks++) {
            uint32_t a[2][4];
#pragma unroll
            for (int mt = 0; mt < 2; mt++) {
                int r = aRow0 + mt * 16;
                int ch = ks * 2 + aChB;
                uint32_t ad = As + r * 128 + ((ch ^ (r & 7)) << 4);
                LDSM_X4(a[mt][0], a[mt][1], a[mt][2], a[mt][3], ad);
            }
            uint32_t b[8][2];
#pragma unroll
            for (int ntp = 0; ntp < 4; ntp++) {
                int n = bN0 + ntp * 16;
                int ch = ks * 2 + bChB;
                uint32_t bd = Bs + n * 128 + ((ch ^ (n & 7)) << 4);
                LDSM_X4(b[2 * ntp][0], b[2 * ntp][1],
                        b[2 * ntp + 1][0], b[2 * ntp + 1][1], bd);
            }
#pragma unroll
            for (int mt = 0; mt < 2; mt++)
#pragma unroll
                for (int nt = 0; nt < 8; nt++)
                    MMA16816(acc[mt][nt], a[mt], b[nt]);
        }

        // issue next load AFTER compute: writes stage (u+2)%3 == (u-1)%3,
        // disjoint from the stage just read; all prior reads of it retired
        // at the barrier above.
        if (u + 2 < 192) PREFETCH(u + 2);

        if ((u % 24) == 23) {
            // fold this n-chunk into the running argmin, reset accumulators
            int nc = u / 24;
#pragma unroll
            for (int mt = 0; mt < 2; mt++) {
#pragma unroll
                for (int nt = 0; nt < 8; nt++) {
                    int code0 = nc * 128 + wn * 64 + nt * 8 + 2 * (lane & 3);
                    float d0 = sCn[code0]     - 2.f * acc[mt][nt][0];
                    float d1 = sCn[code0 + 1] - 2.f * acc[mt][nt][1];
                    float d2 = sCn[code0]     - 2.f * acc[mt][nt][2];
                    float d3 = sCn[code0 + 1] - 2.f * acc[mt][nt][3];
                    int s0 = mt * 2, s1 = mt * 2 + 1;
                    if (d0 < bestD[s0] || (d0 == bestD[s0] && code0     < bestI[s0])) { bestD[s0] = d0; bestI[s0] = code0; }
                    if (d1 < bestD[s0] || (d1 == bestD[s0] && code0 + 1 < bestI[s0])) { bestD[s0] = d1; bestI[s0] = code0 + 1; }
                    if (d2 < bestD[s1] || (d2 == bestD[s1] && code0     < bestI[s1])) { bestD[s1] = d2; bestI[s1] = code0; }
                    if (d3 < bestD[s1] || (d3 == bestD[s1] && code0 + 1 < bestI[s1])) { bestD[s1] = d3; bestI[s1] = code0 + 1; }
#pragma unroll
                    for (int c = 0; c < 4; c++) acc[mt][nt][c] = 0.f;
                }
            }
        }
    }
#undef PREFETCH

    // reduce across the 4 lanes of each quad (same row), then across wn halves
    float* sD = (float*)(smem + SM_SD);
    int*   sI = (int*)(smem + SM_SI);
#pragma unroll
    for (int slot = 0; slot < 4; slot++) {
        float d = bestD[slot]; int i = bestI[slot];
#pragma unroll
        for (int off = 1; off <= 2; off <<= 1) {
            float od = __shfl_xor_sync(0xffffffffu, d, off);
            int   oi = __shfl_xor_sync(0xffffffffu, i, off);
            if (od < d || (od == d && oi < i)) { d = od; i = oi; }
        }
        if ((lane & 3) == 0) {
            int row = wm * 32 + (slot >> 1) * 16 + (lane >> 2) + ((slot & 1) << 3);
            sD[wn * 128 + row] = d;
            sI[wn * 128 + row] = i;
        }
    }
    __syncthreads();

    int* sBest = (int*)(smem + SM_BESTI);
    if (tid < 128) {
        float d0 = sD[tid], d1 = sD[128 + tid];
        int   i0 = sI[tid], i1 = sI[128 + tid];
        int best = (d1 < d0 || (d1 == d0 && i1 < i0)) ? i1 : i0;
        sBest[tid] = best;
        g_idx[q * NTOK + rowBase + tid] = best;
        atomicAdd(&g_hist[q * KCODES + best], 1u);
    }
    __syncthreads();

    // residual update + loss partial + next-stage fp16 split
    float sq = 0.f;
    for (int e = tid; e < 128 * 128; e += 256) {
        int r = e >> 7;
        int c4 = (e & 127) * 4;
        int best = sBest[r];
        size_t ro = (size_t)(rowBase + r) * CDIM + c4;
        float4 rv = *(const float4*)&g_resid[ro];
        float4 cv = __ldg((const float4*)&cbF32[(size_t)best * CDIM + c4]);
        float4 nv = make_float4(rv.x - cv.x, rv.y - cv.y, rv.z - cv.z, rv.w - cv.w);
        *(float4*)&g_resid[ro] = nv;
        __half h0 = __float2half(nv.x), h1 = __float2half(nv.y);
        __half h2 = __float2half(nv.z), h3 = __float2half(nv.w);
        *(__half2*)&g_rHi[ro]     = __halves2half2(h0, h1);
        *(__half2*)&g_rHi[ro + 2] = __halves2half2(h2, h3);
        *(__half2*)&g_rLo[ro] = __halves2half2(
            __float2half(nv.x - __half2float(h0)), __float2half(nv.y - __half2float(h1)));
        *(__half2*)&g_rLo[ro + 2] = __halves2half2(
            __float2half(nv.z - __half2float(h2)), __float2half(nv.w - __half2float(h3)));
        sq += nv.x * nv.x + nv.y * nv.y + nv.z * nv.z + nv.w * nv.w;
    }
    float* sRed = (float*)(smem + SM_RED);
    sRed[tid] = sq;
    __syncthreads();
#pragma unroll
    for (int s2 = 128; s2 > 0; s2 >>= 1) {
        if (tid < s2) sRed[tid] += sRed[tid + s2];
        __syncthreads();
    }
    if (tid == 0) g_lossPart[q][blockIdx.x] = sRed[0];
}

// ---------------------------------------------------------------------------
__global__ void quant_out_kernel(const float* __restrict__ x, float* __restrict__ out) {
    __shared__ float tile[32][33];
    int n = blockIdx.z;
    int tBase = blockIdx.x * 32;
    int cBase = blockIdx.y * 32;
    int tx = threadIdx.x, ty = threadIdx.y;
#pragma unroll
    for (int j = 0; j < 4; j++)
        tile[ty + j * 8][tx] =
            g_resid[(size_t)(n * TLEN + tBase + ty + j * 8) * CDIM + cBase + tx];
    __syncthreads();
#pragma unroll
    for (int j = 0; j < 4; j++) {
        int c = cBase + ty + j * 8;
        int t = tBase + tx;
        size_t o = (size_t)n * CDIM * TLEN + (size_t)c * TLEN + t;
        out[o] = x[o] - tile[tx][ty + j * 8];
    }
}

__global__ void idx_out_kernel(float* __restrict__ out) {
    int i = blockIdx.x * blockDim.x + threadIdx.x;
    if (i < NTOK) {
#pragma unroll
        for (int qq = 0; qq < QSTG; qq++)
            out[OUT_IDX_OFF + (size_t)i * QSTG + qq] = (float)g_idx[qq * NTOK + i];
    }
}

__global__ void finalize_kernel(float* __restrict__ out) {
    __shared__ float red[256];
    int tid = threadIdx.x;
    float lossSum = 0.f, perpSum = 0.f;
    for (int qq = 0; qq < QSTG; qq++) {
        red[tid] = g_lossPart[qq][tid];
        __syncthreads();
#pragma unroll
        for (int s = 128; s > 0; s >>= 1) {
            if (tid < s) red[tid] += red[tid + s];
            __syncthreads();
        }
        float loss_q = red[0] / (float)((size_t)NTOK * CDIM);
        __syncthreads();
        float ps = 0.f;
        for (int k = tid; k < KCODES; k += 256) {
            float p = (float)g_hist[qq * KCODES + k] / (32768.0f + 1e-10f);
            ps += p * logf(p + 1e-7f);
        }
        red[tid] = ps;
        __syncthreads();
#pragma unroll
        for (int s = 128; s > 0; s >>= 1) {
            if (tid < s) red[tid] += red[tid + s];
            __syncthreads();
        }
        float perp_q = expf(-red[0]);
        __syncthreads();
        lossSum += loss_q;
        perpSum += perp_q;
    }
    if (tid == 0) {
        out[OUT_SCAL_OFF + 0] = lossSum / (float)QSTG;
        out[OUT_SCAL_OFF + 1] = perpSum / (float)QSTG;
    }
}

// ---------------------------------------------------------------------------
extern "C" void kernel_launch(void* const* d_in, const int* in_sizes, int n_in,
                              void* d_out, int out_size) {
    const float* x  = (const float*)d_in[0];   // (64, 512, 512)
    const float* cb = (const float*)d_in[1];   // (6, 1024, 512)
    float* out = (float*)d_out;

    cudaFuncSetAttribute(vq_stage_mma, cudaFuncAttributeMaxDynamicSharedMemorySize,
                         SMEM_TOTAL);

    init_kernel<<<(QSTG * KCODES + 255) / 256, 256>>>();
    prep_cb<<<QSTG * KCODES, 128>>>(cb);
    prep_resid<<<dim3(TLEN / 32, CDIM / 32, NB), dim3(32, 8)>>>(x);

    for (int q = 0; q < QSTG; q++)
        vq_stage_mma<<<NTOK / 128, 256, SMEM_TOTAL>>>(cb + (size_t)q * KCODES * CDIM, q);

    quant_out_kernel<<<dim3(TLEN / 32, CDIM / 32, NB), dim3(32, 8)>>>(x, out);
    idx_out_kernel<<<(NTOK + 255) / 256, 256>>>(out);
    finalize_kernel<<<1, 256>>>(out);
}

// round 8
// speedup vs baseline: 1.0672x; 1.0672x over previous
#include <cuda_runtime.h>
#include <cuda_fp16.h>
#include <stdint.h>
#include <math.h>

// Problem constants
#define NTOK   32768
#define CDIM   512
#define KCODES 1024
#define QSTG   6
#define NB     64
#define TLEN   512

#define OUT_IDX_OFF  (NB * CDIM * TLEN)
#define OUT_SCAL_OFF (OUT_IDX_OFF + NTOK * QSTG)

// ---- static device scratch ----
__device__ __align__(256) float  g_resid[(size_t)NTOK * CDIM];
__device__ __align__(256) __half g_rHi[(size_t)NTOK * CDIM];
__device__ __align__(256) __half g_rLo[(size_t)NTOK * CDIM];
__device__ __align__(256) __half g_cbHi[(size_t)QSTG * KCODES * CDIM];
__device__ __align__(256) __half g_cbLo[(size_t)QSTG * KCODES * CDIM];
__device__ float        g_cnorm[QSTG * KCODES];
__device__ int          g_idx[QSTG * NTOK];
__device__ unsigned int g_hist[QSTG * KCODES];
__device__ float        g_lossPart[QSTG][NTOK / 128];

// ---- dynamic SMEM layout ----
#define SM_CN     0          // 1024 floats  (4 KB)
#define SM_SD     4096       // 2*128 floats (1 KB)
#define SM_SI     5120       // 2*128 ints   (1 KB)
#define SM_RED    6144       // 256 floats   (1 KB)
#define SM_BESTI  7168       // 128 ints
#define SM_TILES  8192       // 3 stages x (A 16 KB + B 16 KB)
#define STG_BYTES 32768
#define SMEM_TOTAL (8192 + 3 * STG_BYTES)   // 106496

static __device__ __forceinline__ uint32_t smem_u32(const void* p) {
    uint32_t a;
    asm("{ .reg .u64 t; cvta.to.shared.u64 t, %1; cvt.u32.u64 %0, t; }" : "=r"(a) : "l"(p));
    return a;
}

#define CP16(dst, src) \
    asm volatile("cp.async.cg.shared.global [%0], [%1], 16;" :: "r"(dst), "l"(src))
#define CP_COMMIT() asm volatile("cp.async.commit_group;" ::: "memory")
#define CP_WAIT1()  asm volatile("cp.async.wait_group 1;" ::: "memory")
#define CP_WAIT0()  asm volatile("cp.async.wait_group 0;" ::: "memory")

#define LDSM_X4(r0, r1, r2, r3, addr)                                          \
    asm volatile("ldmatrix.sync.aligned.m8n8.x4.shared.b16 {%0,%1,%2,%3}, [%4];" \
        : "=r"(r0), "=r"(r1), "=r"(r2), "=r"(r3) : "r"(addr))

#define MMA16816(d, a, b)                                                      \
    asm volatile("mma.sync.aligned.m16n8k16.row.col.f32.f16.f16.f32 "          \
        "{%0,%1,%2,%3}, {%4,%5,%6,%7}, {%8,%9}, {%0,%1,%2,%3};"                \
        : "+f"((d)[0]), "+f"((d)[1]), "+f"((d)[2]), "+f"((d)[3])               \
        : "r"((a)[0]), "r"((a)[1]), "r"((a)[2]), "r"((a)[3]),                  \
          "r"((b)[0]), "r"((b)[1]))

// ---------------------------------------------------------------------------
__global__ void init_kernel() {
    int i = blockIdx.x * blockDim.x + threadIdx.x;
    if (i < QSTG * KCODES) g_hist[i] = 0u;
}

// per-code: fp16 hi/lo split of codebook + |c|^2
__global__ void prep_cb(const float* __restrict__ cb) {
    __shared__ float red[4];
    int code = blockIdx.x;                    // q*1024 + k
    int tid = threadIdx.x;
    size_t base = (size_t)code * CDIM;
    float4 v = ((const float4*)(cb + base))[tid];
    __half h0 = __float2half(v.x), h1 = __float2half(v.y);
    __half h2 = __float2half(v.z), h3 = __float2half(v.w);
    *(__half2*)&g_cbHi[base + tid * 4]     = __halves2half2(h0, h1);
    *(__half2*)&g_cbHi[base + tid * 4 + 2] = __halves2half2(h2, h3);
    *(__half2*)&g_cbLo[base + tid * 4] = __halves2half2(
        __float2half(v.x - __half2float(h0)), __float2half(v.y - __half2float(h1)));
    *(__half2*)&g_cbLo[base + tid * 4 + 2] = __halves2half2(
        __float2half(v.z - __half2float(h2)), __float2half(v.w - __half2float(h3)));
    float s = v.x * v.x + v.y * v.y + v.z * v.z + v.w * v.w;
#pragma unroll
    for (int off = 16; off > 0; off >>= 1) s += __shfl_down_sync(0xffffffffu, s, off);
    if ((tid & 31) == 0) red[tid >> 5] = s;
    __syncthreads();
    if (tid == 0) g_cnorm[code] = red[0] + red[1] + red[2] + red[3];
}

// transpose x -> residual (NT, C) + fp16 hi/lo
__global__ void prep_resid(const float* __restrict__ x) {
    __shared__ float tile[32][33];
    int n = blockIdx.z;
    int tBase = blockIdx.x * 32;
    int cBase = blockIdx.y * 32;
    int tx = threadIdx.x, ty = threadIdx.y;
#pragma unroll
    for (int j = 0; j < 4; j++)
        tile[ty + j * 8][tx] =
            x[(size_t)n * CDIM * TLEN + (size_t)(cBase + ty + j * 8) * TLEN + tBase + tx];
    __syncthreads();
#pragma unroll
    for (int j = 0; j < 4; j++) {
        float v = tile[tx][ty + j * 8];
        size_t o = (size_t)(n * TLEN + tBase + ty + j * 8) * CDIM + cBase + tx;
        g_resid[o] = v;
        __half h = __float2half(v);
        g_rHi[o] = h;
        g_rLo[o] = __float2half(v - __half2float(h));
    }
}

// ---------------------------------------------------------------------------
// HMMA stage kernel: 3-segment fp16-split GEMM + argmin + residual update.
// 8 n-chunks x 24 k-blocks; 3-stage cp.async pipeline (2 outstanding groups).
// Inner triple unrolled so the stage buffer index (j%3) is compile-time.
// Per sub-iteration: wait_group -> ONE barrier -> prefetch(j+2) -> compute(j).
// Safety: the barrier after the wait gives collective visibility of group j
// AND proves all threads finished compute j-1, so prefetch j+2 (same buffer
// as j-1, since (j+2)%3 == (j-1)%3) never races a reader.
// ---------------------------------------------------------------------------
__global__ __launch_bounds__(256, 2)
void vq_stage_mma(const float* __restrict__ cbF32, int q) {
    extern __shared__ char smem[];
    uint32_t sbase = smem_u32(smem);
    const int tid = threadIdx.x;
    const int lane = tid & 31;
    const int wid = tid >> 5;
    const int wm = wid & 3;        // m-group: rows wm*32..+32
    const int wn = wid >> 2;       // n-group: cols wn*64..+64
    const int rowBase = blockIdx.x * 128;

    float* sCn = (float*)(smem + SM_CN);
#pragma unroll
    for (int i = 0; i < 4; i++) sCn[tid + 256 * i] = g_cnorm[q * KCODES + tid + 256 * i];

    const __half* __restrict__ rHi = g_rHi;
    const __half* __restrict__ rLo = g_rLo;
    const __half* __restrict__ cHi = g_cbHi + (size_t)q * KCODES * CDIM;
    const __half* __restrict__ cLo = g_cbLo + (size_t)q * KCODES * CDIM;

    // per-thread cp.async offsets, computed once (elements / bytes)
    int aGlob[4], bGlob[4], swz[4];
#pragma unroll
    for (int t = 0; t < 4; t++) {
        int ci = tid + 256 * t;
        int row = ci >> 3, ch = ci & 7;
        aGlob[t] = (rowBase + row) * CDIM + ch * 8;
        bGlob[t] = row * CDIM + ch * 8;
        swz[t]   = row * 128 + ((ch ^ (row & 7)) << 4);
    }

    float bestD[4];
    int   bestI[4];
#pragma unroll
    for (int i = 0; i < 4; i++) { bestD[i] = 3.4e38f; bestI[i] = 0; }

    // per-lane ldmatrix address components
    const int aRow0 = wm * 32 + (lane & 15);       // + mt*16
    const int aChB  = lane >> 4;                   // + ks*2
    const int bN0   = wn * 64 + ((lane >> 4) << 3) + (lane & 7);  // + ntp*16
    const int bChB  = (lane >> 3) & 1;             // + ks*2

    float acc[2][8][4];
#pragma unroll
    for (int mt = 0; mt < 2; mt++)
#pragma unroll
        for (int nt = 0; nt < 8; nt++)
#pragma unroll
            for (int c = 0; c < 4; c++) acc[mt][nt][c] = 0.f;

// prefetch one A+B tile pair for within-chunk index t (0..23) of chunk with
// element base bBase, into stage buffer byte offset bufOff (compile-time).
#define PREFETCH_T(tgt, bBase, bufOff) do {                                    \
        const __half* _aP = ((tgt) < 16) ? rHi : rLo;                          \
        const __half* _bP = ((tgt) >= 8 && (tgt) < 16) ? cLo : cHi;            \
        int _kOff = ((tgt) & 7) * 64;                                          \
        _Pragma("unroll")                                                      \
        for (int _t = 0; _t < 4; _t++) {                                       \
            CP16(sbase + SM_TILES + (bufOff) + swz[_t],                        \
                 _aP + aGlob[_t] + _kOff);                                     \
            CP16(sbase + SM_TILES + (bufOff) + 16384 + swz[_t],                \
                 _bP + (bBase) + bGlob[_t] + _kOff);                           \
        }                                                                      \
        CP_COMMIT();                                                           \
    } while (0)

#define COMPUTE(bufOff) do {                                                   \
        uint32_t As = sbase + SM_TILES + (bufOff);                             \
        uint32_t Bs = As + 16384;                                              \
        _Pragma("unroll")                                                      \
        for (int ks = 0; ks < 4; ks++) {                                       \
            uint32_t a[2][4];                                                  \
            _Pragma("unroll")                                                  \
            for (int mt = 0; mt < 2; mt++) {                                   \
                int r = aRow0 + mt * 16;                                       \
                int ch = ks * 2 + aChB;                                        \
                uint32_t ad = As + r * 128 + ((ch ^ (r & 7)) << 4);            \
                LDSM_X4(a[mt][0], a[mt][1], a[mt][2], a[mt][3], ad);           \
            }                                                                  \
            uint32_t b[8][2];                                                  \
            _Pragma("unroll")                                                  \
            for (int ntp = 0; ntp < 4; ntp++) {                                \
                int n = bN0 + ntp * 16;                                        \
                int ch = ks * 2 + bChB;                                        \
                uint32_t bd = Bs + n * 128 + ((ch ^ (n & 7)) << 4);            \
                LDSM_X4(b[2 * ntp][0], b[2 * ntp][1],                          \
                        b[2 * ntp + 1][0], b[2 * ntp + 1][1], bd);             \
            }                                                                  \
            _Pragma("unroll")                                                  \
            for (int mt = 0; mt < 2; mt++)                                     \
                _Pragma("unroll")                                              \
                for (int nt = 0; nt < 8; nt++)                                 \
                    MMA16816(acc[mt][nt], a[mt], b[nt]);                       \
        }                                                                      \
    } while (0)

    // prime the pipeline: (nc=0, j=0) -> buf0, (nc=0, j=1) -> buf1
    PREFETCH_T(0, 0, 0);
    PREFETCH_T(1, 0, STG_BYTES);

    for (int nc = 0; nc < 8; nc++) {
        const int ncBase = nc << 16;               // nc * 128 * 512 elements

        for (int ss = 0; ss < 24; ss += 3) {
            // ---- sub 0: j = ss (buf 0), prefetch j+2 (buf 2, same chunk) ----
            CP_WAIT1();
            __syncthreads();
            PREFETCH_T(ss + 2, ncBase, 2 * STG_BYTES);
            COMPUTE(0);

            // ---- sub 1: j = ss+1 (buf 1), prefetch j+2 = ss+3 (buf 0) ----
            CP_WAIT1();
            __syncthreads();
            {
                int tgt = ss + 3;
                if (tgt < 24) {
                    PREFETCH_T(tgt, ncBase, 0);
                } else if (nc < 7) {               // crosses into next chunk, j'=0
                    PREFETCH_T(0, ncBase + 65536, 0);
                }
            }
            COMPUTE(STG_BYTES);

            // ---- sub 2: j = ss+2 (buf 2), prefetch j+2 = ss+4 (buf 1) ----
            if (ss == 21 && nc == 7) { CP_WAIT0(); } else { CP_WAIT1(); }
            __syncthreads();
            {
                int tgt = ss + 4;
                if (tgt < 24) {
                    PREFETCH_T(tgt, ncBase, STG_BYTES);
                } else if (nc < 7) {               // crosses into next chunk, j'=1
                    PREFETCH_T(1, ncBase + 65536, STG_BYTES);
                }
            }
            COMPUTE(2 * STG_BYTES);
        }

        // fold this n-chunk into the running argmin, reset accumulators
#pragma unroll
        for (int mt = 0; mt < 2; mt++) {
#pragma unroll
            for (int nt = 0; nt < 8; nt++) {
                int code0 = nc * 128 + wn * 64 + nt * 8 + 2 * (lane & 3);
                float d0 = sCn[code0]     - 2.f * acc[mt][nt][0];
                float d1 = sCn[code0 + 1] - 2.f * acc[mt][nt][1];
                float d2 = sCn[code0]     - 2.f * acc[mt][nt][2];
                float d3 = sCn[code0 + 1] - 2.f * acc[mt][nt][3];
                int s0 = mt * 2, s1 = mt * 2 + 1;
                if (d0 < bestD[s0] || (d0 == bestD[s0] && code0     < bestI[s0])) { bestD[s0] = d0; bestI[s0] = code0; }
                if (d1 < bestD[s0] || (d1 == bestD[s0] && code0 + 1 < bestI[s0])) { bestD[s0] = d1; bestI[s0] = code0 + 1; }
                if (d2 < bestD[s1] || (d2 == bestD[s1] && code0     < bestI[s1])) { bestD[s1] = d2; bestI[s1] = code0; }
                if (d3 < bestD[s1] || (d3 == bestD[s1] && code0 + 1 < bestI[s1])) { bestD[s1] = d3; bestI[s1] = code0 + 1; }
#pragma unroll
                for (int c = 0; c < 4; c++) acc[mt][nt][c] = 0.f;
            }
        }
    }
#undef PREFETCH_T
#undef COMPUTE

    // reduce across the 4 lanes of each quad (same row), then across wn halves
    float* sD = (float*)(smem + SM_SD);
    int*   sI = (int*)(smem + SM_SI);
#pragma unroll
    for (int slot = 0; slot < 4; slot++) {
        float d = bestD[slot]; int i = bestI[slot];
#pragma unroll
        for (int off = 1; off <= 2; off <<= 1) {
            float od = __shfl_xor_sync(0xffffffffu, d, off);
            int   oi = __shfl_xor_sync(0xffffffffu, i, off);
            if (od < d || (od == d && oi < i)) { d = od; i = oi; }
        }
        if ((lane & 3) == 0) {
            int row = wm * 32 + (slot >> 1) * 16 + (lane >> 2) + ((slot & 1) << 3);
            sD[wn * 128 + row] = d;
            sI[wn * 128 + row] = i;
        }
    }
    __syncthreads();

    int* sBest = (int*)(smem + SM_BESTI);
    if (tid < 128) {
        float d0 = sD[tid], d1 = sD[128 + tid];
        int   i0 = sI[tid], i1 = sI[128 + tid];
        int best = (d1 < d0 || (d1 == d0 && i1 < i0)) ? i1 : i0;
        sBest[tid] = best;
        g_idx[q * NTOK + rowBase + tid] = best;
        atomicAdd(&g_hist[q * KCODES + best], 1u);
    }
    __syncthreads();

    // residual update + loss partial + next-stage fp16 split
    float sq = 0.f;
    for (int e = tid; e < 128 * 128; e += 256) {
        int r = e >> 7;
        int c4 = (e & 127) * 4;
        int best = sBest[r];
        size_t ro = (size_t)(rowBase + r) * CDIM + c4;
        float4 rv = *(const float4*)&g_resid[ro];
        float4 cv = __ldg((const float4*)&cbF32[(size_t)best * CDIM + c4]);
        float4 nv = make_float4(rv.x - cv.x, rv.y - cv.y, rv.z - cv.z, rv.w - cv.w);
        *(float4*)&g_resid[ro] = nv;
        __half h0 = __float2half(nv.x), h1 = __float2half(nv.y);
        __half h2 = __float2half(nv.z), h3 = __float2half(nv.w);
        *(__half2*)&g_rHi[ro]     = __halves2half2(h0, h1);
        *(__half2*)&g_rHi[ro + 2] = __halves2half2(h2, h3);
        *(__half2*)&g_rLo[ro] = __halves2half2(
            __float2half(nv.x - __half2float(h0)), __float2half(nv.y - __half2float(h1)));
        *(__half2*)&g_rLo[ro + 2] = __halves2half2(
            __float2half(nv.z - __half2float(h2)), __float2half(nv.w - __half2float(h3)));
        sq += nv.x * nv.x + nv.y * nv.y + nv.z * nv.z + nv.w * nv.w;
    }
    float* sRed = (float*)(smem + SM_RED);
    sRed[tid] = sq;
    __syncthreads();
#pragma unroll
    for (int s2 = 128; s2 > 0; s2 >>= 1) {
        if (tid < s2) sRed[tid] += sRed[tid + s2];
        __syncthreads();
    }
    if (tid == 0) g_lossPart[q][blockIdx.x] = sRed[0];
}

// ---------------------------------------------------------------------------
__global__ void quant_out_kernel(const float* __restrict__ x, float* __restrict__ out) {
    __shared__ float tile[32][33];
    int n = blockIdx.z;
    int tBase = blockIdx.x * 32;
    int cBase = blockIdx.y * 32;
    int tx = threadIdx.x, ty = threadIdx.y;
#pragma unroll
    for (int j = 0; j < 4; j++)
        tile[ty + j * 8][tx] =
            g_resid[(size_t)(n * TLEN + tBase + ty + j * 8) * CDIM + cBase + tx];
    __syncthreads();
#pragma unroll
    for (int j = 0; j < 4; j++) {
        int c = cBase + ty + j * 8;
        int t = tBase + tx;
        size_t o = (size_t)n * CDIM * TLEN + (size_t)c * TLEN + t;
        out[o] = x[o] - tile[tx][ty + j * 8];
    }
}

__global__ void idx_out_kernel(float* __restrict__ out) {
    int i = blockIdx.x * blockDim.x + threadIdx.x;
    if (i < NTOK) {
#pragma unroll
        for (int qq = 0; qq < QSTG; qq++)
            out[OUT_IDX_OFF + (size_t)i * QSTG + qq] = (float)g_idx[qq * NTOK + i];
    }
}

__global__ void finalize_kernel(float* __restrict__ out) {
    __shared__ float red[256];
    int tid = threadIdx.x;
    float lossSum = 0.f, perpSum = 0.f;
    for (int qq = 0; qq < QSTG; qq++) {
        red[tid] = g_lossPart[qq][tid];
        __syncthreads();
#pragma unroll
        for (int s = 128; s > 0; s >>= 1) {
            if (tid < s) red[tid] += red[tid + s];
            __syncthreads();
        }
        float loss_q = red[0] / (float)((size_t)NTOK * CDIM);
        __syncthreads();
        float ps = 0.f;
        for (int k = tid; k < KCODES; k += 256) {
            float p = (float)g_hist[qq * KCODES + k] / (32768.0f + 1e-10f);
            ps += p * logf(p + 1e-7f);
        }
        red[tid] = ps;
        __syncthreads();
#pragma unroll
        for (int s = 128; s > 0; s >>= 1) {
            if (tid < s) red[tid] += red[tid + s];
            __syncthreads();
        }
        float perp_q = expf(-red[0]);
        __syncthreads();
        lossSum += loss_q;
        perpSum += perp_q;
    }
    if (tid == 0) {
        out[OUT_SCAL_OFF + 0] = lossSum / (float)QSTG;
        out[OUT_SCAL_OFF + 1] = perpSum / (float)QSTG;
    }
}

// ---------------------------------------------------------------------------
extern "C" void kernel_launch(void* const* d_in, const int* in_sizes, int n_in,
                              void* d_out, int out_size) {
    const float* x  = (const float*)d_in[0];   // (64, 512, 512)
    const float* cb = (const float*)d_in[1];   // (6, 1024, 512)
    float* out = (float*)d_out;

    cudaFuncSetAttribute(vq_stage_mma, cudaFuncAttributeMaxDynamicSharedMemorySize,
                         SMEM_TOTAL);

    init_kernel<<<(QSTG * KCODES + 255) / 256, 256>>>();
    prep_cb<<<QSTG * KCODES, 128>>>(cb);
    prep_resid<<<dim3(TLEN / 32, CDIM / 32, NB), dim3(32, 8)>>>(x);

    for (int q = 0; q < QSTG; q++)
        vq_stage_mma<<<NTOK / 128, 256, SMEM_TOTAL>>>(cb + (size_t)q * KCODES * CDIM, q);

    quant_out_kernel<<<dim3(TLEN / 32, CDIM / 32, NB), dim3(32, 8)>>>(x, out);
    idx_out_kernel<<<(NTOK + 255) / 256, 256>>>(out);
    finalize_kernel<<<1, 256>>>(out);
}

// round 10
// speedup vs baseline: 1.2313x; 1.1538x over previous
#include <cuda_runtime.h>
#include <cuda_fp16.h>
#include <stdint.h>
#include <math.h>

// Problem constants
#define NTOK   32768
#define CDIM   512
#define KCODES 1024
#define QSTG   6
#define NB     64
#define TLEN   512

#define OUT_IDX_OFF  (NB * CDIM * TLEN)
#define OUT_SCAL_OFF (OUT_IDX_OFF + NTOK * QSTG)

// ---- static device scratch ----
__device__ __align__(256) float  g_resid[(size_t)NTOK * CDIM];
__device__ __align__(256) __half g_rHi[(size_t)NTOK * CDIM];
__device__ __align__(256) __half g_rLo[(size_t)NTOK * CDIM];
__device__ __align__(256) __half g_cbHi[(size_t)QSTG * KCODES * CDIM];
__device__ __align__(256) __half g_cbLo[(size_t)QSTG * KCODES * CDIM];
__device__ float        g_cnorm[QSTG * KCODES];
__device__ int          g_idx[QSTG * NTOK];
__device__ unsigned int g_hist[QSTG * KCODES];
__device__ float        g_lossPart[QSTG][NTOK / 128];
__device__ float        g_rn2Hi[NTOK];         // ||rHi||^2 per token
__device__ float        g_rn2Lo[NTOK];         // ||rLo||^2 per token
__device__ float        g_cbMaxHi[QSTG];       // max_k ||cHi_k||
__device__ float        g_cbMaxLo[QSTG];       // max_k ||cLo_k||
__device__ unsigned int g_flagCnt[QSTG];
__device__ int          g_flagList[NTOK];
__device__ unsigned long long g_bestKey[NTOK]; // packed (ordered-dist, idx)

// ---- dynamic SMEM layout (pass kernels) ----
#define SM_CN     0          // 1024 floats (4 KB)
#define SM_SD     4096       // 2*128 floats
#define SM_SI     5120       // 2*128 ints
#define SM_SD2    6144       // 2*128 floats (second-best)
#define SM_LIST   7168       // 128 ints (pass2)
#define SM_TILES  8192       // 2 stages x (A 16 KB + B 16 KB)
#define STG_BYTES 32768
#define PASS_SMEM (8192 + 2 * STG_BYTES)   // 73728

static __device__ __forceinline__ uint32_t smem_u32(const void* p) {
    uint32_t a;
    asm("{ .reg .u64 t; cvta.to.shared.u64 t, %1; cvt.u32.u64 %0, t; }" : "=r"(a) : "l"(p));
    return a;
}

// order-preserving (distance, index) key: min key == (min dist, then min idx)
static __device__ __forceinline__ unsigned long long packKey(float d, int idx) {
    unsigned u = __float_as_uint(d);
    u = (u & 0x80000000u) ? ~u : (u | 0x80000000u);
    return ((unsigned long long)u << 32) | (unsigned)idx;
}

#define CP16(dst, src) \
    asm volatile("cp.async.cg.shared.global [%0], [%1], 16;" :: "r"(dst), "l"(src))
#define CP_COMMIT() asm volatile("cp.async.commit_group;" ::: "memory")
#define CP_WAIT0()  asm volatile("cp.async.wait_group 0;" ::: "memory")

#define LDSM_X4(r0, r1, r2, r3, addr)                                          \
    asm volatile("ldmatrix.sync.aligned.m8n8.x4.shared.b16 {%0,%1,%2,%3}, [%4];" \
        : "=r"(r0), "=r"(r1), "=r"(r2), "=r"(r3) : "r"(addr))

#define MMA16816(d, a, b)                                                      \
    asm volatile("mma.sync.aligned.m16n8k16.row.col.f32.f16.f16.f32 "          \
        "{%0,%1,%2,%3}, {%4,%5,%6,%7}, {%8,%9}, {%0,%1,%2,%3};"                \
        : "+f"((d)[0]), "+f"((d)[1]), "+f"((d)[2]), "+f"((d)[3])               \
        : "r"((a)[0]), "r"((a)[1]), "r"((a)[2]), "r"((a)[3]),                  \
          "r"((b)[0]), "r"((b)[1]))

// warp-tile compute of one 128x128x64 k-block from smem buffer at byte bufOff
#define COMPUTE_BLK(bufOff) do {                                               \
        uint32_t As = sbase + SM_TILES + (bufOff);                             \
        uint32_t Bs = As + 16384;                                              \
        _Pragma("unroll")                                                      \
        for (int ks = 0; ks < 4; ks++) {                                       \
            uint32_t a[2][4];                                                  \
            _Pragma("unroll")                                                  \
            for (int mt = 0; mt < 2; mt++) {                                   \
                int r = aRow0 + mt * 16;                                       \
                int ch = ks * 2 + aChB;                                        \
                uint32_t ad = As + r * 128 + ((ch ^ (r & 7)) << 4);            \
                LDSM_X4(a[mt][0], a[mt][1], a[mt][2], a[mt][3], ad);           \
            }                                                                  \
            uint32_t b[8][2];                                                  \
            _Pragma("unroll")                                                  \
            for (int ntp = 0; ntp < 4; ntp++) {                                \
                int n = bN0 + ntp * 16;                                        \
                int ch = ks * 2 + bChB;                                        \
                uint32_t bd = Bs + n * 128 + ((ch ^ (n & 7)) << 4);            \
                LDSM_X4(b[2 * ntp][0], b[2 * ntp][1],                          \
                        b[2 * ntp + 1][0], b[2 * ntp + 1][1], bd);             \
            }                                                                  \
            _Pragma("unroll")                                                  \
            for (int mt = 0; mt < 2; mt++)                                     \
                _Pragma("unroll")                                              \
                for (int nt = 0; nt < 8; nt++)                                 \
                    MMA16816(acc[mt][nt], a[mt], b[nt]);                       \
        }                                                                      \
    } while (0)

// ---------------------------------------------------------------------------
__global__ void init_kernel() {
    int i = blockIdx.x * blockDim.x + threadIdx.x;
    if (i < QSTG * KCODES) g_hist[i] = 0u;
    if (i < QSTG) {
        g_flagCnt[i] = 0u;
        g_cbMaxHi[i] = 0.f;
        g_cbMaxLo[i] = 0.f;
    }
}

// per-code: fp16 hi/lo split + |c|^2 (fp32) + per-stage max ||cHi||,||cLo||
__global__ void prep_cb(const float* __restrict__ cb) {
    __shared__ float redN[4], redH[4], redL[4];
    int code = blockIdx.x;                    // q*1024 + k
    int qq = code >> 10;
    int tid = threadIdx.x;
    size_t base = (size_t)code * CDIM;
    float4 v = ((const float4*)(cb + base))[tid];
    __half h0 = __float2half(v.x), h1 = __float2half(v.y);
    __half h2 = __float2half(v.z), h3 = __float2half(v.w);
    float hf0 = __half2float(h0), hf1 = __half2float(h1);
    float hf2 = __half2float(h2), hf3 = __half2float(h3);
    float lf0 = v.x - hf0, lf1 = v.y - hf1, lf2 = v.z - hf2, lf3 = v.w - hf3;
    *(__half2*)&g_cbHi[base + tid * 4]     = __halves2half2(h0, h1);
    *(__half2*)&g_cbHi[base + tid * 4 + 2] = __halves2half2(h2, h3);
    *(__half2*)&g_cbLo[base + tid * 4] = __halves2half2(
        __float2half(lf0), __float2half(lf1));
    *(__half2*)&g_cbLo[base + tid * 4 + 2] = __halves2half2(
        __float2half(lf2), __float2half(lf3));
    float sn = v.x * v.x + v.y * v.y + v.z * v.z + v.w * v.w;
    float sh = hf0 * hf0 + hf1 * hf1 + hf2 * hf2 + hf3 * hf3;
    float sl = lf0 * lf0 + lf1 * lf1 + lf2 * lf2 + lf3 * lf3;
#pragma unroll
    for (int off = 16; off > 0; off >>= 1) {
        sn += __shfl_down_sync(0xffffffffu, sn, off);
        sh += __shfl_down_sync(0xffffffffu, sh, off);
        sl += __shfl_down_sync(0xffffffffu, sl, off);
    }
    if ((tid & 31) == 0) { redN[tid >> 5] = sn; redH[tid >> 5] = sh; redL[tid >> 5] = sl; }
    __syncthreads();
    if (tid == 0) {
        g_cnorm[code] = redN[0] + redN[1] + redN[2] + redN[3];
        float nh = sqrtf(redH[0] + redH[1] + redH[2] + redH[3]);
        float nl = sqrtf(redL[0] + redL[1] + redL[2] + redL[3]);
        atomicMax((int*)&g_cbMaxHi[qq], __float_as_int(nh));
        atomicMax((int*)&g_cbMaxLo[qq], __float_as_int(nl));
    }
}

// transpose x -> residual (NT, C) + fp16 hi/lo
__global__ void prep_resid(const float* __restrict__ x) {
    __shared__ float tile[32][33];
    int n = blockIdx.z;
    int tBase = blockIdx.x * 32;
    int cBase = blockIdx.y * 32;
    int tx = threadIdx.x, ty = threadIdx.y;
#pragma unroll
    for (int j = 0; j < 4; j++)
        tile[ty + j * 8][tx] =
            x[(size_t)n * CDIM * TLEN + (size_t)(cBase + ty + j * 8) * TLEN + tBase + tx];
    __syncthreads();
#pragma unroll
    for (int j = 0; j < 4; j++) {
        float v = tile[tx][ty + j * 8];
        size_t o = (size_t)(n * TLEN + tBase + ty + j * 8) * CDIM + cBase + tx;
        g_resid[o] = v;
        __half h = __float2half(v);
        g_rHi[o] = h;
        g_rLo[o] = __float2half(v - __half2float(h));
    }
}

// initial per-token ||rHi||^2 / ||rLo||^2 (one warp per token)
__global__ void norm0_kernel() {
    int token = blockIdx.x * 8 + (threadIdx.x >> 5);
    int lane = threadIdx.x & 31;
    const __half2* h = (const __half2*)(g_rHi + (size_t)token * CDIM);
    const __half2* l = (const __half2*)(g_rLo + (size_t)token * CDIM);
    float sh = 0.f, sl = 0.f;
#pragma unroll
    for (int i = 0; i < 8; i++) {
        float2 hv = __half22float2(h[lane + 32 * i]);
        float2 lv = __half22float2(l[lane + 32 * i]);
        sh += hv.x * hv.x + hv.y * hv.y;
        sl += lv.x * lv.x + lv.y * lv.y;
    }
#pragma unroll
    for (int off = 16; off > 0; off >>= 1) {
        sh += __shfl_down_sync(0xffffffffu, sh, off);
        sl += __shfl_down_sync(0xffffffffu, sl, off);
    }
    if (lane == 0) { g_rn2Hi[token] = sh; g_rn2Lo[token] = sl; }
}

// ---------------------------------------------------------------------------
// Pass 1: hi*hi GEMM (K=512, 8 k-blocks) + best/second-best argmin + flagging
// ---------------------------------------------------------------------------
__global__ __launch_bounds__(256, 2)
void vq_pass1(int q) {
    extern __shared__ char smem[];
    uint32_t sbase = smem_u32(smem);
    const int tid = threadIdx.x;
    const int lane = tid & 31;
    const int wid = tid >> 5;
    const int wm = wid & 3;
    const int wn = wid >> 2;
    const int rowBase = blockIdx.x * 128;

    float* sCn = (float*)(smem + SM_CN);
#pragma unroll
    for (int i = 0; i < 4; i++) sCn[tid + 256 * i] = g_cnorm[q * KCODES + tid + 256 * i];

    const __half* __restrict__ rHi = g_rHi;
    const __half* __restrict__ cHi = g_cbHi + (size_t)q * KCODES * CDIM;

    int aGlob[4], bGlob[4], swz[4];
#pragma unroll
    for (int t = 0; t < 4; t++) {
        int ci = tid + 256 * t;
        int row = ci >> 3, ch = ci & 7;
        aGlob[t] = (rowBase + row) * CDIM + ch * 8;
        bGlob[t] = row * CDIM + ch * 8;
        swz[t]   = row * 128 + ((ch ^ (row & 7)) << 4);
    }

    float bestD[4], best2D[4];
    int   bestI[4];
#pragma unroll
    for (int i = 0; i < 4; i++) { bestD[i] = 3.4e38f; best2D[i] = 3.4e38f; bestI[i] = 0; }

    const int aRow0 = wm * 32 + (lane & 15);
    const int aChB  = lane >> 4;
    const int bN0   = wn * 64 + ((lane >> 4) << 3) + (lane & 7);
    const int bChB  = (lane >> 3) & 1;

    float acc[2][8][4];
#pragma unroll
    for (int mt = 0; mt < 2; mt++)
#pragma unroll
        for (int nt = 0; nt < 8; nt++)
#pragma unroll
            for (int c = 0; c < 4; c++) acc[mt][nt][c] = 0.f;

#define PF1(ncB, kb, bufOff) do {                                              \
        int _k = (kb) * 64;                                                    \
        _Pragma("unroll")                                                      \
        for (int _t = 0; _t < 4; _t++) {                                       \
            CP16(sbase + SM_TILES + (bufOff) + swz[_t], rHi + aGlob[_t] + _k); \
            CP16(sbase + SM_TILES + (bufOff) + 16384 + swz[_t],                \
                 cHi + (ncB) + bGlob[_t] + _k);                                \
        }                                                                      \
        CP_COMMIT();                                                           \
    } while (0)

    PF1(0, 0, 0);

    for (int nc = 0; nc < 8; nc++) {
        const int ncB = nc << 16;
        const int ncB2 = (nc + 1) << 16;
#pragma unroll
        for (int kb2 = 0; kb2 < 4; kb2++) {
            CP_WAIT0();
            __syncthreads();
            PF1(ncB, 2 * kb2 + 1, STG_BYTES);
            COMPUTE_BLK(0);

            CP_WAIT0();
            __syncthreads();
            if (kb2 < 3) { PF1(ncB, 2 * kb2 + 2, 0); }
            else if (nc < 7) { PF1(ncB2, 0, 0); }
            COMPUTE_BLK(STG_BYTES);
        }

        // fold with best + second-best tracking
#pragma unroll
        for (int mt = 0; mt < 2; mt++) {
#pragma unroll
            for (int nt = 0; nt < 8; nt++) {
                int code0 = nc * 128 + wn * 64 + nt * 8 + 2 * (lane & 3);
#pragma unroll
                for (int c = 0; c < 4; c++) {
                    int s = mt * 2 + (c >> 1);
                    int cj = code0 + (c & 1);
                    float d = sCn[cj] - 2.f * acc[mt][nt][c];
                    if (d < bestD[s] || (d == bestD[s] && cj < bestI[s])) {
                        best2D[s] = bestD[s]; bestD[s] = d; bestI[s] = cj;
                    } else if (d < best2D[s]) {
                        best2D[s] = d;
                    }
                    acc[mt][nt][c] = 0.f;
                }
            }
        }
    }
#undef PF1

    // quad-lane reduce (keep best + second-best), then cross-warp via smem
    float* sD  = (float*)(smem + SM_SD);
    int*   sI  = (int*)(smem + SM_SI);
    float* sD2 = (float*)(smem + SM_SD2);
#pragma unroll
    for (int slot = 0; slot < 4; slot++) {
        float d1 = bestD[slot], d2 = best2D[slot];
        int i1 = bestI[slot];
#pragma unroll
        for (int off = 1; off <= 2; off <<= 1) {
            float od1 = __shfl_xor_sync(0xffffffffu, d1, off);
            int   oi1 = __shfl_xor_sync(0xffffffffu, i1, off);
            float od2 = __shfl_xor_sync(0xffffffffu, d2, off);
            if (od1 < d1 || (od1 == d1 && oi1 < i1)) {
                d2 = fminf(d1, od2); d1 = od1; i1 = oi1;
            } else {
                d2 = fminf(od1, d2);
            }
        }
        if ((lane & 3) == 0) {
            int row = wm * 32 + (slot >> 1) * 16 + (lane >> 2) + ((slot & 1) << 3);
            sD[wn * 128 + row] = d1;
            sI[wn * 128 + row] = i1;
            sD2[wn * 128 + row] = d2;
        }
    }
    __syncthreads();

    if (tid < 128) {
        float d1 = sD[tid], d2 = sD2[tid];
        int   i1 = sI[tid];
        float e1 = sD[128 + tid], e2 = sD2[128 + tid];
        int   j1 = sI[128 + tid];
        float b1, b2; int bi;
        if (e1 < d1 || (e1 == d1 && j1 < i1)) { b1 = e1; bi = j1; b2 = fminf(d1, e2); }
        else                                  { b1 = d1; bi = i1; b2 = fminf(e1, d2); }
        int token = rowBase + tid;
        g_idx[q * NTOK + token] = bi;
        // rigorous certificate: per-code |d_true - d_hi| <= E; need gap > 2E
        float rnH = sqrtf(g_rn2Hi[token]);
        float rnL = sqrtf(g_rn2Lo[token]);
        float mH = g_cbMaxHi[q], mL = g_cbMaxLo[q];
        float E = 2.f * (rnH * mL + rnL * mH + rnL * mL);
        if (b2 - b1 <= 2.f * E + 0.05f) {
            g_bestKey[token] = 0xFFFFFFFFFFFFFFFFull;
            int p = atomicAdd(&g_flagCnt[q], 1u);
            g_flagList[p] = token;
        }
    }
}

// ---------------------------------------------------------------------------
// Pass 2: full 3-segment split GEMM for flagged tokens, parallel over
// (tile, nc) pairs; merge via order-independent atomicMin on packed keys.
// ---------------------------------------------------------------------------
__global__ __launch_bounds__(256, 2)
void vq_pass2(int q) {
    extern __shared__ char smem[];
    uint32_t sbase = smem_u32(smem);
    const int tid = threadIdx.x;
    const int lane = tid & 31;
    const int wid = tid >> 5;
    const int wm = wid & 3;
    const int wn = wid >> 2;

    int cnt = (int)g_flagCnt[q];
    if (cnt == 0) return;
    int npairs = ((cnt + 127) >> 7) << 3;     // tiles * 8 n-chunks

    float* sCn = (float*)(smem + SM_CN);
#pragma unroll
    for (int i = 0; i < 4; i++) sCn[tid + 256 * i] = g_cnorm[q * KCODES + tid + 256 * i];
    int* sList = (int*)(smem + SM_LIST);

    const __half* __restrict__ rHi = g_rHi;
    const __half* __restrict__ rLo = g_rLo;
    const __half* __restrict__ cHi = g_cbHi + (size_t)q * KCODES * CDIM;
    const __half* __restrict__ cLo = g_cbLo + (size_t)q * KCODES * CDIM;

    int rowA[4], chA[4], bGlob[4], swz[4];
#pragma unroll
    for (int t = 0; t < 4; t++) {
        int ci = tid + 256 * t;
        rowA[t] = ci >> 3;
        chA[t]  = (ci & 7) * 8;
        bGlob[t] = rowA[t] * CDIM + chA[t];
        swz[t]   = rowA[t] * 128 + (((ci & 7) ^ (rowA[t] & 7)) << 4);
    }

    const int aRow0 = wm * 32 + (lane & 15);
    const int aChB  = lane >> 4;
    const int bN0   = wn * 64 + ((lane >> 4) << 3) + (lane & 7);
    const int bChB  = (lane >> 3) & 1;

    for (int pair = blockIdx.x; pair < npairs; pair += gridDim.x) {
        int tile = pair >> 3;
        int nc = pair & 7;
        const int ncB = nc << 16;

        __syncthreads();                       // prior pair's smem reads done
        if (tid < 128) {
            int ii = tile * 128 + tid;
            sList[tid] = (ii < cnt) ? g_flagList[ii] : g_flagList[0];
        }
        __syncthreads();

        int aBase[4];
#pragma unroll
        for (int t = 0; t < 4; t++) aBase[t] = sList[rowA[t]] * CDIM + chA[t];

        float bestD[4];
        int   bestI[4];
#pragma unroll
        for (int i = 0; i < 4; i++) { bestD[i] = 3.4e38f; bestI[i] = 0; }

        float acc[2][8][4];
#pragma unroll
        for (int mt = 0; mt < 2; mt++)
#pragma unroll
            for (int nt = 0; nt < 8; nt++)
#pragma unroll
                for (int c = 0; c < 4; c++) acc[mt][nt][c] = 0.f;

#define PF2(v, bufOff) do {                                                    \
        const __half* _aP = ((v) < 16) ? rHi : rLo;                            \
        const __half* _bP = ((v) >= 8 && (v) < 16) ? cLo : cHi;                \
        int _k = ((v) & 7) * 64;                                               \
        _Pragma("unroll")                                                      \
        for (int _t = 0; _t < 4; _t++) {                                       \
            CP16(sbase + SM_TILES + (bufOff) + swz[_t], _aP + aBase[_t] + _k); \
            CP16(sbase + SM_TILES + (bufOff) + 16384 + swz[_t],                \
                 _bP + ncB + bGlob[_t] + _k);                                  \
        }                                                                      \
        CP_COMMIT();                                                           \
    } while (0)

        PF2(0, 0);
        for (int v = 0; v < 24; v++) {
            CP_WAIT0();
            __syncthreads();
            if (v + 1 < 24) PF2(v + 1, ((v + 1) & 1) * STG_BYTES);
            COMPUTE_BLK((v & 1) * STG_BYTES);
        }
#undef PF2

        // fold single-best over this 128-code chunk
#pragma unroll
        for (int mt = 0; mt < 2; mt++) {
#pragma unroll
            for (int nt = 0; nt < 8; nt++) {
                int code0 = nc * 128 + wn * 64 + nt * 8 + 2 * (lane & 3);
#pragma unroll
                for (int c = 0; c < 4; c++) {
                    int s = mt * 2 + (c >> 1);
                    int cj = code0 + (c & 1);
                    float d = sCn[cj] - 2.f * acc[mt][nt][c];
                    if (d < bestD[s] || (d == bestD[s] && cj < bestI[s])) {
                        bestD[s] = d; bestI[s] = cj;
                    }
                }
            }
        }

        float* sD = (float*)(smem + SM_SD);
        int*   sI = (int*)(smem + SM_SI);
#pragma unroll
        for (int slot = 0; slot < 4; slot++) {
            float d = bestD[slot]; int i = bestI[slot];
#pragma unroll
            for (int off = 1; off <= 2; off <<= 1) {
                float od = __shfl_xor_sync(0xffffffffu, d, off);
                int   oi = __shfl_xor_sync(0xffffffffu, i, off);
                if (od < d || (od == d && oi < i)) { d = od; i = oi; }
            }
            if ((lane & 3) == 0) {
                int row = wm * 32 + (slot >> 1) * 16 + (lane >> 2) + ((slot & 1) << 3);
                sD[wn * 128 + row] = d;
                sI[wn * 128 + row] = i;
            }
        }
        __syncthreads();
        if (tid < 128 && tile * 128 + tid < cnt) {
            float d0 = sD[tid], d1 = sD[128 + tid];
            int   i0 = sI[tid], i1 = sI[128 + tid];
            unsigned long long key =
                (d1 < d0 || (d1 == d0 && i1 < i0)) ? packKey(d1, i1) : packKey(d0, i0);
            atomicMin(&g_bestKey[sList[tid]], key);
        }
    }
}

// scatter merged keys back into g_idx (flagged tokens only)
__global__ void vq_merge(int q) {
    int i = blockIdx.x * blockDim.x + threadIdx.x;
    if (i < (int)g_flagCnt[q]) {
        int token = g_flagList[i];
        g_idx[q * NTOK + token] = (int)(g_bestKey[token] & 0xFFFFFFFFu);
    }
}

// ---------------------------------------------------------------------------
// K3: residual update + loss + hist + re-split + next-stage norms
// ---------------------------------------------------------------------------
__global__ void vq_update(const float* __restrict__ cbF32, int q) {
    __shared__ float sH2[256], sL2[256], sSq[256];
    const int tid = threadIdx.x;
    const int row = tid & 127;
    const int half = tid >> 7;
    const int rowBase = blockIdx.x * 128;
    const int token = rowBase + row;
    const int best = g_idx[q * NTOK + token];

    const float4* cbP = (const float4*)(cbF32 + (size_t)best * CDIM + half * 256);
    float4* rP = (float4*)(g_resid + (size_t)token * CDIM + half * 256);
    __half2* hP = (__half2*)(g_rHi + (size_t)token * CDIM + half * 256);
    __half2* lP = (__half2*)(g_rLo + (size_t)token * CDIM + half * 256);

    float sq = 0.f, h2 = 0.f, l2 = 0.f;
#pragma unroll 8
    for (int j = 0; j < 64; j++) {
        float4 rv = rP[j];
        float4 cv = __ldg(cbP + j);
        float4 nv = make_float4(rv.x - cv.x, rv.y - cv.y, rv.z - cv.z, rv.w - cv.w);
        rP[j] = nv;
        __half hh0 = __float2half(nv.x), hh1 = __float2half(nv.y);
        __half hh2 = __float2half(nv.z), hh3 = __float2half(nv.w);
        float hf0 = __half2float(hh0), hf1 = __half2float(hh1);
        float hf2 = __half2float(hh2), hf3 = __half2float(hh3);
        float lf0 = nv.x - hf0, lf1 = nv.y - hf1, lf2 = nv.z - hf2, lf3 = nv.w - hf3;
        hP[2 * j]     = __halves2half2(hh0, hh1);
        hP[2 * j + 1] = __halves2half2(hh2, hh3);
        lP[2 * j]     = __halves2half2(__float2half(lf0), __float2half(lf1));
        lP[2 * j + 1] = __halves2half2(__float2half(lf2), __float2half(lf3));
        sq += nv.x * nv.x + nv.y * nv.y + nv.z * nv.z + nv.w * nv.w;
        h2 += hf0 * hf0 + hf1 * hf1 + hf2 * hf2 + hf3 * hf3;
        l2 += lf0 * lf0 + lf1 * lf1 + lf2 * lf2 + lf3 * lf3;
    }
    sH2[tid] = h2; sL2[tid] = l2; sSq[tid] = sq;
    __syncthreads();
    if (tid < 128) {
        g_rn2Hi[token] = sH2[tid] + sH2[tid + 128];
        g_rn2Lo[token] = sL2[tid] + sL2[tid + 128];
        atomicAdd(&g_hist[q * KCODES + best], 1u);
    }
#pragma unroll
    for (int s = 128; s > 0; s >>= 1) {
        if (tid < s) sSq[tid] += sSq[tid + s];
        __syncthreads();
    }
    if (tid == 0) g_lossPart[q][blockIdx.x] = sSq[0];
}

// ---------------------------------------------------------------------------
__global__ void quant_out_kernel(const float* __restrict__ x, float* __restrict__ out) {
    __shared__ float tile[32][33];
    int n = blockIdx.z;
    int tBase = blockIdx.x * 32;
    int cBase = blockIdx.y * 32;
    int tx = threadIdx.x, ty = threadIdx.y;
#pragma unroll
    for (int j = 0; j < 4; j++)
        tile[ty + j * 8][tx] =
            g_resid[(size_t)(n * TLEN + tBase + ty + j * 8) * CDIM + cBase + tx];
    __syncthreads();
#pragma unroll
    for (int j = 0; j < 4; j++) {
        int c = cBase + ty + j * 8;
        int t = tBase + tx;
        size_t o = (size_t)n * CDIM * TLEN + (size_t)c * TLEN + t;
        out[o] = x[o] - tile[tx][ty + j * 8];
    }
}

__global__ void idx_out_kernel(float* __restrict__ out) {
    int i = blockIdx.x * blockDim.x + threadIdx.x;
    if (i < NTOK) {
#pragma unroll
        for (int qq = 0; qq < QSTG; qq++)
            out[OUT_IDX_OFF + (size_t)i * QSTG + qq] = (float)g_idx[qq * NTOK + i];
    }
}

__global__ void finalize_kernel(float* __restrict__ out) {
    __shared__ float red[256];
    int tid = threadIdx.x;
    float lossSum = 0.f, perpSum = 0.f;
    for (int qq = 0; qq < QSTG; qq++) {
        red[tid] = g_lossPart[qq][tid];
        __syncthreads();
#pragma unroll
        for (int s = 128; s > 0; s >>= 1) {
            if (tid < s) red[tid] += red[tid + s];
            __syncthreads();
        }
        float loss_q = red[0] / (float)((size_t)NTOK * CDIM);
        __syncthreads();
        float ps = 0.f;
        for (int k = tid; k < KCODES; k += 256) {
            float p = (float)g_hist[qq * KCODES + k] / (32768.0f + 1e-10f);
            ps += p * logf(p + 1e-7f);
        }
        red[tid] = ps;
        __syncthreads();
#pragma unroll
        for (int s = 128; s > 0; s >>= 1) {
            if (tid < s) red[tid] += red[tid + s];
            __syncthreads();
        }
        float perp_q = expf(-red[0]);
        __syncthreads();
        lossSum += loss_q;
        perpSum += perp_q;
    }
    if (tid == 0) {
        out[OUT_SCAL_OFF + 0] = lossSum / (float)QSTG;
        out[OUT_SCAL_OFF + 1] = perpSum / (float)QSTG;
    }
}

// ---------------------------------------------------------------------------
extern "C" void kernel_launch(void* const* d_in, const int* in_sizes, int n_in,
                              void* d_out, int out_size) {
    const float* x  = (const float*)d_in[0];   // (64, 512, 512)
    const float* cb = (const float*)d_in[1];   // (6, 1024, 512)
    float* out = (float*)d_out;

    cudaFuncSetAttribute(vq_pass1, cudaFuncAttributeMaxDynamicSharedMemorySize, PASS_SMEM);
    cudaFuncSetAttribute(vq_pass2, cudaFuncAttributeMaxDynamicSharedMemorySize, PASS_SMEM);

    init_kernel<<<24, 256>>>();
    prep_cb<<<QSTG * KCODES, 128>>>(cb);
    prep_resid<<<dim3(TLEN / 32, CDIM / 32, NB), dim3(32, 8)>>>(x);
    norm0_kernel<<<NTOK / 8, 256>>>();

    for (int q = 0; q < QSTG; q++) {
        vq_pass1<<<NTOK / 128, 256, PASS_SMEM>>>(q);
        vq_pass2<<<128, 256, PASS_SMEM>>>(q);
        vq_merge<<<NTOK / 256, 256>>>(q);
        vq_update<<<NTOK / 128, 256>>>(cb + (size_t)q * KCODES * CDIM, q);
    }

    quant_out_kernel<<<dim3(TLEN / 32, CDIM / 32, NB), dim3(32, 8)>>>(x, out);
    idx_out_kernel<<<(NTOK + 255) / 256, 256>>>(out);
    finalize_kernel<<<1, 256>>>(out);
}